// round 3
// baseline (speedup 1.0000x reference)
#include <cuda_runtime.h>

#define D 64
#define MAXN 100000
#define MAXE 1250000
#define NLAYERS 3
#define BN_EPS 1e-5f
#define TILE 64

typedef unsigned long long ull;

#define PK2(d, s)  asm("mov.b64 %0, {%1, %1};" : "=l"(d) : "f"(s))
#define FMA2(d, a, b, c) asm("fma.rn.f32x2 %0, %1, %2, %3;" : "=l"(d) : "l"(a), "l"(b), "l"(c))
#define UPK2(lo, hi, s) asm("mov.b64 {%0, %1}, %2;" : "=f"(lo), "=f"(hi) : "l"(s))

// ---------------- static device scratch -------------------------------------
__device__ int   g_deg[MAXN];
__device__ int   g_rowptr[MAXN + 1];
__device__ int   g_cursor[MAXN];
__device__ int   g_blocksums[256];
__device__ int   g_srcsorted[MAXE];
__device__ __align__(16) float g_hA[(size_t)MAXN * D];
__device__ __align__(16) float g_hB[(size_t)MAXN * D];
__device__ float g_colsum[D];
__device__ float g_colsq[D];
__device__ float g_scale[D];
__device__ float g_shift[D];

// ---------------- CSR build --------------------------------------------------
__global__ void k_zero_deg(int N) {
    int i = blockIdx.x * blockDim.x + threadIdx.x;
    if (i < N) g_deg[i] = 0;
}

__global__ void k_hist(const int* __restrict__ ei, int E) {
    int e = blockIdx.x * blockDim.x + threadIdx.x;
    if (e < E) atomicAdd(&g_deg[ei[E + e]], 1);
}

__global__ void k_scan1(int N) {
    __shared__ int sh[256];
    int tid = threadIdx.x;
    int base = blockIdx.x * 1024 + tid * 4;
    int v0 = (base + 0 < N) ? g_deg[base + 0] : 0;
    int v1 = (base + 1 < N) ? g_deg[base + 1] : 0;
    int v2 = (base + 2 < N) ? g_deg[base + 2] : 0;
    int v3 = (base + 3 < N) ? g_deg[base + 3] : 0;
    int t0 = v0, t1 = t0 + v1, t2 = t1 + v2, t3 = t2 + v3;
    sh[tid] = t3;
    __syncthreads();
    for (int off = 1; off < 256; off <<= 1) {
        int add = (tid >= off) ? sh[tid - off] : 0;
        __syncthreads();
        sh[tid] += add;
        __syncthreads();
    }
    int excl = sh[tid] - t3;
    if (base + 0 < N) g_rowptr[base + 1] = excl + t0;
    if (base + 1 < N) g_rowptr[base + 2] = excl + t1;
    if (base + 2 < N) g_rowptr[base + 3] = excl + t2;
    if (base + 3 < N) g_rowptr[base + 4] = excl + t3;
    if (tid == 255) g_blocksums[blockIdx.x] = sh[255];
}

__global__ void k_scan2(int NB) {
    __shared__ int sh[256];
    int t = threadIdx.x;
    int v = (t < NB) ? g_blocksums[t] : 0;
    sh[t] = v;
    __syncthreads();
    for (int off = 1; off < 256; off <<= 1) {
        int a = (t >= off) ? sh[t - off] : 0;
        __syncthreads();
        sh[t] += a;
        __syncthreads();
    }
    if (t < NB) g_blocksums[t] = sh[t] - v;   // exclusive
}

__global__ void k_scan3(int N) {
    int base = blockIdx.x * 1024 + threadIdx.x * 4;
    int off = g_blocksums[blockIdx.x];
#pragma unroll
    for (int i = 0; i < 4; i++)
        if (base + i < N) g_rowptr[base + 1 + i] += off;
    if (blockIdx.x == 0 && threadIdx.x == 0) g_rowptr[0] = 0;
}

__global__ void k_copy_cursor(int N) {
    int i = blockIdx.x * blockDim.x + threadIdx.x;
    if (i < N) g_cursor[i] = g_rowptr[i];
}

__global__ void k_bucket(const int* __restrict__ ei, int E) {
    int e = blockIdx.x * blockDim.x + threadIdx.x;
    if (e < E) {
        int d = ei[E + e];
        int pos = atomicAdd(&g_cursor[d], 1);
        g_srcsorted[pos] = ei[e];
    }
}

__global__ void k_zero_stats() {
    int t = threadIdx.x;
    if (t < D) { g_colsum[t] = 0.f; g_colsq[t] = 0.f; }
}

// ---------------- fused layer: gather + dual GEMM + BN stats ----------------
// smem layout (floats):
//   wa[4096] | wb[4096] | m[64*66] | x[64*66] | br[64] | sum[64] | sq[64]
#define OFF_WB  4096
#define OFF_M   8192
#define OFF_X   12416
#define OFF_BR  16640
#define OFF_SUM 16704
#define OFF_SQ  16768
#define SMEM_FLOATS 16832
#define MROW 66

template<int TF>
__global__ void __launch_bounds__(256) k_layer(
    const float* __restrict__ x_src, float* __restrict__ h_out,
    const float* __restrict__ Wrel, const float* __restrict__ brel,
    const float* __restrict__ Wroot, int N)
{
    extern __shared__ float smem[];
    float* wa_sh = smem;
    float* wb_sh = smem + OFF_WB;
    float* m_sh  = smem + OFF_M;
    float* x_sh  = smem + OFF_X;
    float* s_br  = smem + OFF_BR;
    float* s_sum = smem + OFF_SUM;
    float* s_sq  = smem + OFF_SQ;

    int tid = threadIdx.x;
    int lane = tid & 31;
    int w = tid >> 5;

    // preamble: stage weights + bias, zero stats
    for (int i = tid; i < 1024; i += 256) {
        ((float4*)wa_sh)[i] = ((const float4*)Wrel)[i];
        ((float4*)wb_sh)[i] = ((const float4*)Wroot)[i];
    }
    if (tid < D) { s_br[tid] = brel[tid]; }
    if (tid >= 64 && tid < 128) { s_sum[tid - 64] = 0.f; s_sq[tid - 64] = 0.f; }

    // per-lane BN transform constants (for TF=1)
    float2 sc2, sh2;
    if (TF) {
        sc2 = ((const float2*)g_scale)[lane];
        sh2 = ((const float2*)g_shift)[lane];
    }

    int tile0 = blockIdx.x * TILE;

    // ---------- phase A: gather (msg + root) into smem tiles ----------
    for (int j = 0; j < 8; j++) {
        int r = w * 8 + j;
        int node = tile0 + r;
        if (node < N) {
            const float2* xr = (const float2*)(x_src + (size_t)node * D);
            float2 xv = xr[lane];
            if (TF) {
                xv.x = fmaxf(fmaf(xv.x, sc2.x, sh2.x), 0.f);
                xv.y = fmaxf(fmaf(xv.y, sc2.y, sh2.y), 0.f);
            }
            ((float2*)(x_sh + r * MROW))[lane] = xv;

            float2 mv = make_float2(0.f, 0.f);
            int rs = g_rowptr[node], re = g_rowptr[node + 1];
            for (int base = rs; base < re; base += 32) {
                int jj = base + lane;
                int sj = (jj < re) ? g_srcsorted[jj] : 0;
                int cnt = min(32, re - base);
                int u = 0;
                for (; u + 4 <= cnt; u += 4) {
                    int s0 = __shfl_sync(0xffffffffu, sj, u);
                    int s1 = __shfl_sync(0xffffffffu, sj, u + 1);
                    int s2 = __shfl_sync(0xffffffffu, sj, u + 2);
                    int s3 = __shfl_sync(0xffffffffu, sj, u + 3);
                    float2 a0 = ((const float2*)(x_src + (size_t)s0 * D))[lane];
                    float2 a1 = ((const float2*)(x_src + (size_t)s1 * D))[lane];
                    float2 a2 = ((const float2*)(x_src + (size_t)s2 * D))[lane];
                    float2 a3 = ((const float2*)(x_src + (size_t)s3 * D))[lane];
                    if (TF) {
                        a0.x = fmaxf(fmaf(a0.x, sc2.x, sh2.x), 0.f); a0.y = fmaxf(fmaf(a0.y, sc2.y, sh2.y), 0.f);
                        a1.x = fmaxf(fmaf(a1.x, sc2.x, sh2.x), 0.f); a1.y = fmaxf(fmaf(a1.y, sc2.y, sh2.y), 0.f);
                        a2.x = fmaxf(fmaf(a2.x, sc2.x, sh2.x), 0.f); a2.y = fmaxf(fmaf(a2.y, sc2.y, sh2.y), 0.f);
                        a3.x = fmaxf(fmaf(a3.x, sc2.x, sh2.x), 0.f); a3.y = fmaxf(fmaf(a3.y, sc2.y, sh2.y), 0.f);
                    }
                    mv.x += (a0.x + a1.x) + (a2.x + a3.x);
                    mv.y += (a0.y + a1.y) + (a2.y + a3.y);
                }
                for (; u < cnt; u++) {
                    int s0 = __shfl_sync(0xffffffffu, sj, u);
                    float2 a0 = ((const float2*)(x_src + (size_t)s0 * D))[lane];
                    if (TF) {
                        a0.x = fmaxf(fmaf(a0.x, sc2.x, sh2.x), 0.f);
                        a0.y = fmaxf(fmaf(a0.y, sc2.y, sh2.y), 0.f);
                    }
                    mv.x += a0.x; mv.y += a0.y;
                }
            }
            ((float2*)(m_sh + r * MROW))[lane] = mv;
        } else {
            ((float2*)(x_sh + r * MROW))[lane] = make_float2(0.f, 0.f);
            ((float2*)(m_sh + r * MROW))[lane] = make_float2(0.f, 0.f);
        }
    }
    __syncthreads();

    // ---------- phase B: block-tiled dual GEMM (FFMA2) ----------
    int r = tid >> 2;
    int cg = tid & 3;
    int c0 = cg * 16;
    int node = tile0 + r;
    bool valid = node < N;

    ull acc[8];
    {
        const ull* br2 = (const ull*)s_br;
#pragma unroll
        for (int q = 0; q < 8; q++) acc[q] = br2[cg * 8 + q];
    }

    const float* mrow = m_sh + r * MROW;
    const float* xrow = x_sh + r * MROW;
#pragma unroll 4
    for (int k = 0; k < D; k++) {
        float mr = mrow[k];
        float xr = xrow[k];
        ull mrr, xrr;
        PK2(mrr, mr);
        PK2(xrr, xr);
        const ulonglong2* wa2 = (const ulonglong2*)(wa_sh + k * D + c0);
        const ulonglong2* wb2 = (const ulonglong2*)(wb_sh + k * D + c0);
        ulonglong2 A0 = wa2[0], A1 = wa2[1], A2 = wa2[2], A3 = wa2[3];
        FMA2(acc[0], mrr, A0.x, acc[0]); FMA2(acc[1], mrr, A0.y, acc[1]);
        FMA2(acc[2], mrr, A1.x, acc[2]); FMA2(acc[3], mrr, A1.y, acc[3]);
        FMA2(acc[4], mrr, A2.x, acc[4]); FMA2(acc[5], mrr, A2.y, acc[5]);
        FMA2(acc[6], mrr, A3.x, acc[6]); FMA2(acc[7], mrr, A3.y, acc[7]);
        ulonglong2 B0 = wb2[0], B1 = wb2[1], B2 = wb2[2], B3 = wb2[3];
        FMA2(acc[0], xrr, B0.x, acc[0]); FMA2(acc[1], xrr, B0.y, acc[1]);
        FMA2(acc[2], xrr, B1.x, acc[2]); FMA2(acc[3], xrr, B1.y, acc[3]);
        FMA2(acc[4], xrr, B2.x, acc[4]); FMA2(acc[5], xrr, B2.y, acc[5]);
        FMA2(acc[6], xrr, B3.x, acc[6]); FMA2(acc[7], xrr, B3.y, acc[7]);
    }

    float h[16];
#pragma unroll
    for (int q = 0; q < 8; q++) UPK2(h[2 * q], h[2 * q + 1], acc[q]);
    if (!valid) {
#pragma unroll
        for (int q = 0; q < 16; q++) h[q] = 0.f;
    }

    // BN stats: reduce over the 8 rows this warp owns (lanes differing in bits 2..4)
    float s[16], q2[16];
#pragma unroll
    for (int q = 0; q < 16; q++) { s[q] = h[q]; q2[q] = h[q] * h[q]; }
#pragma unroll
    for (int off = 4; off <= 16; off <<= 1) {
#pragma unroll
        for (int q = 0; q < 16; q++) {
            s[q]  += __shfl_xor_sync(0xffffffffu, s[q], off);
            q2[q] += __shfl_xor_sync(0xffffffffu, q2[q], off);
        }
    }
    if (lane < 4) {
#pragma unroll
        for (int q = 0; q < 16; q++) {
            atomicAdd(&s_sum[lane * 16 + q], s[q]);
            atomicAdd(&s_sq[lane * 16 + q], q2[q]);
        }
    }

    if (valid) {
        float4* out = (float4*)(h_out + (size_t)node * D + c0);
        out[0] = make_float4(h[0], h[1], h[2], h[3]);
        out[1] = make_float4(h[4], h[5], h[6], h[7]);
        out[2] = make_float4(h[8], h[9], h[10], h[11]);
        out[3] = make_float4(h[12], h[13], h[14], h[15]);
    }

    __syncthreads();
    if (tid < 64) atomicAdd(&g_colsum[tid], s_sum[tid]);
    else if (tid < 128) atomicAdd(&g_colsq[tid - 64], s_sq[tid - 64]);
}

__global__ void k_bn(const float* __restrict__ gamma, const float* __restrict__ beta, float invN) {
    int t = threadIdx.x;
    if (t < D) {
        float mean = g_colsum[t] * invN;
        float var  = g_colsq[t] * invN - mean * mean;
        var = var < 0.f ? 0.f : var;
        float sc = gamma[t] * rsqrtf(var + BN_EPS);
        g_scale[t] = sc;
        g_shift[t] = beta[t] - mean * sc;
    }
}

// ---------------- pooling + classifier (applies final BN+ReLU inline) -------
__global__ void k_pool(const float* __restrict__ hfin, const int* __restrict__ batch, int N,
                       const float* __restrict__ Wcls, const float* __restrict__ bcls,
                       float* __restrict__ out)
{
    __shared__ float s_pool[D];
    int g = blockIdx.x, tid = threadIdx.x;

    int lo = 0, hi = N;
    while (lo < hi) { int mid = (lo + hi) >> 1; if (batch[mid] < g) lo = mid + 1; else hi = mid; }
    int start = lo;
    hi = N;
    while (lo < hi) { int mid = (lo + hi) >> 1; if (batch[mid] < g + 1) lo = mid + 1; else hi = mid; }
    int end = lo;

    if (tid < D) s_pool[tid] = 0.f;
    __syncthreads();

    int col = tid & 63, rg = tid >> 6;
    float sc = g_scale[col], sh_ = g_shift[col];
    float p = 0.f;
    for (int r = start + rg; r < end; r += 4)
        p += fmaxf(fmaf(hfin[(size_t)r * D + col], sc, sh_), 0.f);
    atomicAdd(&s_pool[col], p);
    __syncthreads();

    float cnt = (float)(end - start);
    float denom = cnt > 1.f ? cnt : 1.f;
    if (tid < D) s_pool[tid] /= denom;
    __syncthreads();

    if (tid < 10) {
        float acc = bcls[tid];
#pragma unroll
        for (int d = 0; d < D; d++) acc = fmaf(s_pool[d], Wcls[d * 10 + tid], acc);
        out[g * 10 + tid] = acc;
    }
}

// ---------------- launch -----------------------------------------------------
extern "C" void kernel_launch(void* const* d_in, const int* in_sizes, int n_in,
                              void* d_out, int out_size)
{
    const float* x     = (const float*)d_in[0];
    const int*   ei    = (const int*)d_in[1];
    const int*   batch = (const int*)d_in[2];
    const float* Wrel  = (const float*)d_in[3];
    const float* brel  = (const float*)d_in[4];
    const float* Wroot = (const float*)d_in[5];
    const float* gamma = (const float*)d_in[6];
    const float* beta  = (const float*)d_in[7];
    const float* Wcls  = (const float*)d_in[8];
    const float* bcls  = (const float*)d_in[9];
    float* out = (float*)d_out;

    int N = in_sizes[0] / D;
    int E = in_sizes[1] / 2;
    int G = out_size / 10;
    int NB = (N + 1023) / 1024;
    float invN = 1.f / (float)N;
    int NTILES = (N + TILE - 1) / TILE;
    size_t smemb = SMEM_FLOATS * sizeof(float);

    static int attr_done = 0;
    if (!attr_done) {
        cudaFuncSetAttribute(k_layer<0>, cudaFuncAttributeMaxDynamicSharedMemorySize, (int)smemb);
        cudaFuncSetAttribute(k_layer<1>, cudaFuncAttributeMaxDynamicSharedMemorySize, (int)smemb);
        attr_done = 1;
    }

    float *hA, *hB;
    cudaGetSymbolAddress((void**)&hA, g_hA);
    cudaGetSymbolAddress((void**)&hB, g_hB);

    // CSR build (reused by all layers)
    k_zero_deg<<<(N + 255) / 256, 256>>>(N);
    k_hist<<<(E + 255) / 256, 256>>>(ei, E);
    k_scan1<<<NB, 256>>>(N);
    k_scan2<<<1, 256>>>(NB);
    k_scan3<<<NB, 256>>>(N);
    k_copy_cursor<<<(N + 255) / 256, 256>>>(N);
    k_bucket<<<(E + 255) / 256, 256>>>(ei, E);

    // layer 0: x -> hA   (no input transform)
    k_zero_stats<<<1, 64>>>();
    k_layer<0><<<NTILES, 256, smemb>>>(x, hA, Wrel, brel, Wroot, N);
    k_bn<<<1, 64>>>(gamma, beta, invN);

    // layer 1: hA -> hB  (BN+ReLU of layer 0 fused into loads)
    k_zero_stats<<<1, 64>>>();
    k_layer<1><<<NTILES, 256, smemb>>>(hA, hB, Wrel + 4096, brel + 64, Wroot + 4096, N);
    k_bn<<<1, 64>>>(gamma + 64, beta + 64, invN);

    // layer 2: hB -> hA
    k_zero_stats<<<1, 64>>>();
    k_layer<1><<<NTILES, 256, smemb>>>(hB, hA, Wrel + 8192, brel + 128, Wroot + 8192, N);
    k_bn<<<1, 64>>>(gamma + 128, beta + 128, invN);

    // pool (applies layer-2 BN+ReLU inline) + classifier
    k_pool<<<G, 256>>>(hA, batch, N, Wcls, bcls, out);
}